// round 1
// baseline (speedup 1.0000x reference)
#include <cuda_runtime.h>
#include <math.h>

#define NROWS   2048
#define DIM     256
#define SLEN    1024
#define TOUT    512
#define NBATCH  2
#define LSTRIDE 512
#define LN_EPS  1e-5f
#define TWOPI_F 6.283185307179586f

// Scratch (allocation-free rule: __device__ globals)
__device__ float g_Y[NROWS * DIM];   // x @ M^T (pre-LN)
__device__ float g_Z[NROWS * DIM];   // LayerNorm(Y)
__device__ float g_R[NROWS * DIM];   // x @ res_W^T
__device__ float g_T[NROWS * DIM];   // cosine-modulated contraction result

// ---------------------------------------------------------------------------
// K1: C[m][n] = sum_k A[m][k] * B[n][k]  (A: MxK row-major, B: NxK row-major)
// outsel: 0 -> g_Y, 1 -> g_R
// ---------------------------------------------------------------------------
__global__ __launch_bounds__(256) void gemm_abT_kernel(
    const float* __restrict__ A, const float* __restrict__ B,
    int M_, int N_, int K_, int outsel)
{
    __shared__ float As[16][64];
    __shared__ float Bs[16][64];

    const int tid = threadIdx.x;
    const int tx = tid & 15;     // n micro
    const int ty = tid >> 4;     // m micro
    const int m0 = blockIdx.y * 64;
    const int n0 = blockIdx.x * 64;

    float acc[4][4] = {};

    for (int k0 = 0; k0 < K_; k0 += 16) {
#pragma unroll
        for (int l = 0; l < 4; l++) {
            int e = tid + l * 256;        // 0..1023
            int r = e >> 4;               // 0..63
            int c = e & 15;               // 0..15
            As[c][r] = A[(m0 + r) * K_ + k0 + c];
            Bs[c][r] = B[(n0 + r) * K_ + k0 + c];
        }
        __syncthreads();
#pragma unroll
        for (int kk = 0; kk < 16; kk++) {
            float4 a = *reinterpret_cast<const float4*>(&As[kk][ty * 4]);
            float4 b = *reinterpret_cast<const float4*>(&Bs[kk][tx * 4]);
            float av[4] = {a.x, a.y, a.z, a.w};
            float bv[4] = {b.x, b.y, b.z, b.w};
#pragma unroll
            for (int i = 0; i < 4; i++)
#pragma unroll
                for (int j = 0; j < 4; j++)
                    acc[i][j] = fmaf(av[i], bv[j], acc[i][j]);
        }
        __syncthreads();
    }

    float* C = outsel ? g_R : g_Y;
#pragma unroll
    for (int i = 0; i < 4; i++)
#pragma unroll
        for (int j = 0; j < 4; j++)
            C[(m0 + ty * 4 + i) * N_ + n0 + tx * 4 + j] = acc[i][j];
}

// ---------------------------------------------------------------------------
// K2: LayerNorm rows of g_Y -> g_Z.  One warp per row.
// ---------------------------------------------------------------------------
__global__ __launch_bounds__(256) void ln_kernel(
    const float* __restrict__ gamma, const float* __restrict__ beta)
{
    const int warp = threadIdx.x >> 5;
    const int lane = threadIdx.x & 31;
    const int row  = blockIdx.x * 8 + warp;
    const float* y = g_Y + row * DIM;

    float v[8];
    float s = 0.f;
#pragma unroll
    for (int l = 0; l < 8; l++) { v[l] = y[lane + l * 32]; s += v[l]; }
#pragma unroll
    for (int o = 16; o > 0; o >>= 1) s += __shfl_xor_sync(0xffffffffu, s, o);
    const float mu = s * (1.0f / DIM);

    float s2 = 0.f;
#pragma unroll
    for (int l = 0; l < 8; l++) { float d = v[l] - mu; s2 = fmaf(d, d, s2); }
#pragma unroll
    for (int o = 16; o > 0; o >>= 1) s2 += __shfl_xor_sync(0xffffffffu, s2, o);
    const float inv = rsqrtf(s2 * (1.0f / DIM) + LN_EPS);

#pragma unroll
    for (int l = 0; l < 8; l++) {
        int c = lane + l * 32;
        g_Z[row * DIM + c] = (v[l] - mu) * inv * gamma[c] + beta[c];
    }
}

// ---------------------------------------------------------------------------
// K3: T[k,i] = sum_j Z[k,j] * P[i,j] * cos(2*pi*k / (i*256 + j + 2))
// Block: 64 k x 32 i tile, 256 threads, micro-tile 4k x 2i per thread.
// Exact integer reduction: q = rint(k/p); km = fma(-p,q,k) is exact; |arg|<=3pi.
// ---------------------------------------------------------------------------
__global__ __launch_bounds__(256) void tphi_kernel(const float* __restrict__ P)
{
    __shared__ float Zs[64][33];
    __shared__ float Ps[32][33];
    __shared__ float Ip[32][33];   // 1/p
    __shared__ float Pf[32][33];   // p

    const int tid = threadIdx.x;
    const int tx = tid & 15;       // i micro (tx and tx+16)
    const int ty = tid >> 4;       // k micro (ty*4 .. ty*4+3)
    const int k0 = blockIdx.y * 64;
    const int i0 = blockIdx.x * 32;

    float kf[4];
#pragma unroll
    for (int r = 0; r < 4; r++) kf[r] = (float)(k0 + ty * 4 + r);

    float acc[4][2] = {};

    for (int jc = 0; jc < DIM; jc += 32) {
#pragma unroll
        for (int l = 0; l < 8; l++) {      // Z tile: 64x32
            int e = tid + l * 256;
            int r = e >> 5, c = e & 31;
            Zs[r][c] = g_Z[(k0 + r) * DIM + jc + c];
        }
#pragma unroll
        for (int l = 0; l < 4; l++) {      // P / period tiles: 32x32
            int e = tid + l * 256;
            int r = e >> 5, c = e & 31;
            Ps[r][c] = P[(i0 + r) * DIM + jc + c];
            float pf = (float)((i0 + r) * DIM + (jc + c) + 2);
            Pf[r][c] = pf;
            Ip[r][c] = 1.0f / pf;
        }
        __syncthreads();

#pragma unroll 8
        for (int jj = 0; jj < 32; jj++) {
            float z[4];
#pragma unroll
            for (int r = 0; r < 4; r++) z[r] = Zs[ty * 4 + r][jj];
#pragma unroll
            for (int c = 0; c < 2; c++) {
                const int il = tx + c * 16;
                const float pv = Ps[il][jj];
                const float ip = Ip[il][jj];
                const float pf = Pf[il][jj];
                const float tw = TWOPI_F * ip;
#pragma unroll
                for (int r = 0; r < 4; r++) {
                    float u  = kf[r] * ip;
                    float q  = rintf(u);
                    float km = fmaf(-pf, q, kf[r]);    // exact: k mod p (up to +-p)
                    float cv = __cosf(km * tw);
                    acc[r][c] = fmaf(z[r] * pv, cv, acc[r][c]);
                }
            }
        }
        __syncthreads();
    }

#pragma unroll
    for (int r = 0; r < 4; r++)
#pragma unroll
        for (int c = 0; c < 2; c++)
            g_T[(k0 + ty * 4 + r) * DIM + i0 + tx + c * 16] = acc[r][c];
}

// ---------------------------------------------------------------------------
// K4: out[b*512+t][d] = sum_s L[s][t]*T[b*1024+s][d] + rL[s][t]*R[b*1024+s][d]
// Block: 64 t x 64 d tile per batch; BK = 32 over s.
// ---------------------------------------------------------------------------
__global__ __launch_bounds__(256) void linker_kernel(
    const float* __restrict__ L, const float* __restrict__ rL,
    float* __restrict__ out)
{
    __shared__ float Ls[32][64];
    __shared__ float Gs[32][64];
    __shared__ float Ts[32][64];
    __shared__ float Rs[32][64];

    const int tid = threadIdx.x;
    const int tx = tid & 15;     // d micro
    const int ty = tid >> 4;     // t micro
    const int b  = blockIdx.z;
    const int t0 = blockIdx.y * 64;
    const int d0 = blockIdx.x * 64;

    float acc[4][4] = {};

    for (int s0 = 0; s0 < SLEN; s0 += 32) {
#pragma unroll
        for (int l = 0; l < 8; l++) {
            int e = tid + l * 256;       // 0..2047
            int sr = e >> 6, cc = e & 63;
            Ls[sr][cc] = L [(s0 + sr) * LSTRIDE + t0 + cc];
            Gs[sr][cc] = rL[(s0 + sr) * LSTRIDE + t0 + cc];
            Ts[sr][cc] = g_T[((b << 10) + s0 + sr) * DIM + d0 + cc];
            Rs[sr][cc] = g_R[((b << 10) + s0 + sr) * DIM + d0 + cc];
        }
        __syncthreads();
#pragma unroll
        for (int kk = 0; kk < 32; kk++) {
            float4 a  = *reinterpret_cast<const float4*>(&Ls[kk][ty * 4]);
            float4 ag = *reinterpret_cast<const float4*>(&Gs[kk][ty * 4]);
            float4 bt = *reinterpret_cast<const float4*>(&Ts[kk][tx * 4]);
            float4 br = *reinterpret_cast<const float4*>(&Rs[kk][tx * 4]);
            float av[4]  = {a.x, a.y, a.z, a.w};
            float agv[4] = {ag.x, ag.y, ag.z, ag.w};
            float bv[4]  = {bt.x, bt.y, bt.z, bt.w};
            float brv[4] = {br.x, br.y, br.z, br.w};
#pragma unroll
            for (int i = 0; i < 4; i++)
#pragma unroll
                for (int j = 0; j < 4; j++) {
                    acc[i][j] = fmaf(av[i],  bv[j],  acc[i][j]);
                    acc[i][j] = fmaf(agv[i], brv[j], acc[i][j]);
                }
        }
        __syncthreads();
    }

#pragma unroll
    for (int i = 0; i < 4; i++)
#pragma unroll
        for (int j = 0; j < 4; j++)
            out[(b * TOUT + t0 + ty * 4 + i) * DIM + d0 + tx * 4 + j] = acc[i][j];
}

// ---------------------------------------------------------------------------
extern "C" void kernel_launch(void* const* d_in, const int* in_sizes, int n_in,
                              void* d_out, int out_size)
{
    const float* x       = (const float*)d_in[0];   // [2048, 256]
    const float* Mw      = (const float*)d_in[1];   // [256, 256]
    const float* P       = (const float*)d_in[2];   // [256, 256]
    const float* Linker  = (const float*)d_in[3];   // [1024, 512]
    const float* gamma   = (const float*)d_in[4];   // [256]
    const float* beta    = (const float*)d_in[5];   // [256]
    const float* resW    = (const float*)d_in[6];   // [256, 256]
    const float* rLinker = (const float*)d_in[7];   // [1024, 512]
    float* out = (float*)d_out;                     // [1024, 256]

    // K1: Y = x @ M^T ; R = x @ res_W^T
    dim3 g1(DIM / 64, NROWS / 64);
    gemm_abT_kernel<<<g1, 256>>>(x, Mw,   NROWS, DIM, DIM, 0);
    gemm_abT_kernel<<<g1, 256>>>(x, resW, NROWS, DIM, DIM, 1);

    // K2: Z = LayerNorm(Y)
    ln_kernel<<<NROWS / 8, 256>>>(gamma, beta);

    // K3: T (cosine-modulated contraction)
    dim3 g3(DIM / 32, NROWS / 64);
    tphi_kernel<<<g3, 256>>>(P);

    // K4: out = Linker^T-contract(T) + res_linker^T-contract(R)
    dim3 g4(DIM / 64, TOUT / 64, NBATCH);
    linker_kernel<<<g4, 256>>>(Linker, rLinker, out);
}

// round 3
// speedup vs baseline: 1.9979x; 1.9979x over previous
#include <cuda_runtime.h>
#include <math.h>

#define NROWS   2048
#define DIM     256
#define SLEN    1024
#define TOUT    512
#define NBATCH  2
#define LSTRIDE 512
#define LN_EPS  1e-5f
#define TWOPI_F 6.283185307179586f

// Scratch (allocation-free rule: __device__ globals)
__device__ float  g_Y[NROWS * DIM];
__device__ float  g_Z[NROWS * DIM];
__device__ float  g_R[NROWS * DIM];
__device__ float  g_T[NROWS * DIM];
__device__ float4 g_Par[DIM * DIM];                 // {P, 1/p, p, 2cos(2pi/p)}
__device__ float  g_part[4][NBATCH * TOUT * DIM];   // split-K partials

// ---------------------------------------------------------------------------
// K0: per-(i,j) parameter table (k-independent, computed once)
// ---------------------------------------------------------------------------
__global__ __launch_bounds__(256) void param_kernel(const float* __restrict__ P)
{
    int idx = blockIdx.x * 256 + threadIdx.x;       // 0..65535
    int i = idx >> 8, j = idx & 255;
    float pf = (float)(i * DIM + j + 2);
    float ip = 1.0f / pf;                           // IEEE div (precompute, cheap)
    float c2d = 2.0f * cosf(TWOPI_F * ip);          // accurate cos for recurrence coeff
    float4 v; v.x = P[idx]; v.y = ip; v.z = pf; v.w = c2d;
    g_Par[idx] = v;
}

// ---------------------------------------------------------------------------
// K1: fused dual GEMM: Y = x@M^T, R = x@resW^T  (shared x tiles)
// tile 32m x 64n, 128 threads, micro 4x4, grid (4, 64) = 256 blocks
// ---------------------------------------------------------------------------
__global__ __launch_bounds__(128) void dual_gemm_kernel(
    const float* __restrict__ x, const float* __restrict__ Mw,
    const float* __restrict__ Rw)
{
    __shared__ float As[16][36];
    __shared__ float B1[16][68];
    __shared__ float B2[16][68];

    const int tid = threadIdx.x;
    const int tx = tid & 15;          // n micro
    const int ty = tid >> 4;          // m micro (0..7)
    const int m0 = blockIdx.y * 32;
    const int n0 = blockIdx.x * 64;

    float aY[4][4] = {}, aR[4][4] = {};

    for (int k0 = 0; k0 < DIM; k0 += 16) {
#pragma unroll
        for (int l = 0; l < 4; l++) {
            int e = tid + l * 128; int r = e >> 4, c = e & 15;
            As[c][r] = x[(m0 + r) * DIM + k0 + c];
        }
#pragma unroll
        for (int l = 0; l < 8; l++) {
            int e = tid + l * 128; int r = e >> 4, c = e & 15;
            B1[c][r] = Mw[(n0 + r) * DIM + k0 + c];
            B2[c][r] = Rw[(n0 + r) * DIM + k0 + c];
        }
        __syncthreads();
#pragma unroll
        for (int kk = 0; kk < 16; kk++) {
            float4 av = *(const float4*)&As[kk][ty * 4];
            float4 b1 = *(const float4*)&B1[kk][tx * 4];
            float4 b2 = *(const float4*)&B2[kk][tx * 4];
            float a[4]  = {av.x, av.y, av.z, av.w};
            float v1[4] = {b1.x, b1.y, b1.z, b1.w};
            float v2[4] = {b2.x, b2.y, b2.z, b2.w};
#pragma unroll
            for (int i = 0; i < 4; i++)
#pragma unroll
                for (int j = 0; j < 4; j++) {
                    aY[i][j] = fmaf(a[i], v1[j], aY[i][j]);
                    aR[i][j] = fmaf(a[i], v2[j], aR[i][j]);
                }
        }
        __syncthreads();
    }

#pragma unroll
    for (int i = 0; i < 4; i++) {
        float4 vy = {aY[i][0], aY[i][1], aY[i][2], aY[i][3]};
        float4 vr = {aR[i][0], aR[i][1], aR[i][2], aR[i][3]};
        int row = m0 + ty * 4 + i;
        *(float4*)&g_Y[row * DIM + n0 + tx * 4] = vy;
        *(float4*)&g_R[row * DIM + n0 + tx * 4] = vr;
    }
}

// ---------------------------------------------------------------------------
// K2: LayerNorm rows of g_Y -> g_Z.  One warp per row.
// ---------------------------------------------------------------------------
__global__ __launch_bounds__(256) void ln_kernel(
    const float* __restrict__ gamma, const float* __restrict__ beta)
{
    const int warp = threadIdx.x >> 5;
    const int lane = threadIdx.x & 31;
    const int row  = blockIdx.x * 8 + warp;
    const float* y = g_Y + row * DIM;

    float v[8];
    float s = 0.f;
#pragma unroll
    for (int l = 0; l < 8; l++) { v[l] = y[lane + l * 32]; s += v[l]; }
#pragma unroll
    for (int o = 16; o > 0; o >>= 1) s += __shfl_xor_sync(0xffffffffu, s, o);
    const float mu = s * (1.0f / DIM);

    float s2 = 0.f;
#pragma unroll
    for (int l = 0; l < 8; l++) { float d = v[l] - mu; s2 = fmaf(d, d, s2); }
#pragma unroll
    for (int o = 16; o > 0; o >>= 1) s2 += __shfl_xor_sync(0xffffffffu, s2, o);
    const float inv = rsqrtf(s2 * (1.0f / DIM) + LN_EPS);

#pragma unroll
    for (int l = 0; l < 8; l++) {
        int c = lane + l * 32;
        g_Z[row * DIM + c] = (v[l] - mu) * inv * gamma[c] + beta[c];
    }
}

// ---------------------------------------------------------------------------
// K3: T[k,i] = sum_j Z[k,j] * P[i,j] * cos(2*pi*k / p_ij),  p_ij = i*256+j+2
// Chebyshev recurrence over 8 consecutive k per thread:
//   d_r = P*cos(theta0 + r*delta),  d_{r+1} = 2cos(delta)*d_r - d_{r-1}
// Seed via exact integer reduction: q=rint(k/p); km=fma(-p,q,k) exact; |th|<=pi.
// tile 64k x 16i, 128 threads (tx: i, ty: k-group), grid (16, 32) = 512 blocks
// ---------------------------------------------------------------------------
__global__ __launch_bounds__(128) void tphi_kernel()
{
    __shared__ float  Zs[32][68];    // [j][k], float4-aligned rows (272B)
    __shared__ float4 Ps[32][17];    // [j][i] params, padded

    const int tid = threadIdx.x;
    const int tx = tid & 15;         // i
    const int ty = tid >> 4;         // k-group 0..7
    const int i0 = blockIdx.x * 16;
    const int k0 = blockIdx.y * 64;

    const float kf0 = (float)(k0 + ty * 8);
    float acc[8] = {};

    for (int jc = 0; jc < DIM; jc += 32) {
#pragma unroll
        for (int l = 0; l < 16; l++) {           // Z tile 64k x 32j (transposed)
            int e = tid + l * 128; int r = e >> 5, c = e & 31;
            Zs[c][r] = g_Z[(k0 + r) * DIM + jc + c];
        }
#pragma unroll
        for (int l = 0; l < 4; l++) {            // param tile 16i x 32j
            int e = tid + l * 128; int jj = e & 31, il = e >> 5;
            Ps[jj][il] = g_Par[((i0 + il) << 8) + jc + jj];
        }
        __syncthreads();

#pragma unroll 8
        for (int jj = 0; jj < 32; jj++) {
            float4 pr = Ps[jj][tx];              // {P, 1/p, p, 2cos(2pi/p)}
            float4 za = *(const float4*)&Zs[jj][ty * 8];
            float4 zb = *(const float4*)&Zs[jj][ty * 8 + 4];

            float tw = TWOPI_F * pr.y;
            float u  = kf0 * pr.y;
            float q  = rintf(u);
            float km = fmaf(-pr.z, q, kf0);      // exact k mod p
            float th = km * tw;                  // |th| <= ~2pi
            float d0 = pr.x * __cosf(th);
            float d1 = pr.x * __cosf(th + tw);

            acc[0] = fmaf(za.x, d0, acc[0]);
            acc[1] = fmaf(za.y, d1, acc[1]);
            float d2 = fmaf(pr.w, d1, -d0);
            acc[2] = fmaf(za.z, d2, acc[2]);
            float d3 = fmaf(pr.w, d2, -d1);
            acc[3] = fmaf(za.w, d3, acc[3]);
            float d4 = fmaf(pr.w, d3, -d2);
            acc[4] = fmaf(zb.x, d4, acc[4]);
            float d5 = fmaf(pr.w, d4, -d3);
            acc[5] = fmaf(zb.y, d5, acc[5]);
            float d6 = fmaf(pr.w, d5, -d4);
            acc[6] = fmaf(zb.z, d6, acc[6]);
            float d7 = fmaf(pr.w, d6, -d5);
            acc[7] = fmaf(zb.w, d7, acc[7]);
        }
        __syncthreads();
    }

#pragma unroll
    for (int r = 0; r < 8; r++)
        g_T[(k0 + ty * 8 + r) * DIM + i0 + tx] = acc[r];
}

// ---------------------------------------------------------------------------
// K4: split-K linker: partial[split] = sum_{s in split} L[s,t]*T[b,s,d]
//                                    + rL[s,t]*R[b,s,d]
// tile 64t x 64d, 256 threads, blockIdx.z = b*4 + split -> 256 blocks
// ---------------------------------------------------------------------------
__global__ __launch_bounds__(256) void linker_kernel(
    const float* __restrict__ L, const float* __restrict__ rL)
{
    __shared__ float Ls[32][64];
    __shared__ float Gs[32][64];
    __shared__ float Ts[32][64];
    __shared__ float Rs[32][64];

    const int tid = threadIdx.x;
    const int tx = tid & 15;     // d micro
    const int ty = tid >> 4;     // t micro
    const int b     = blockIdx.z >> 2;
    const int split = blockIdx.z & 3;
    const int t0 = blockIdx.y * 64;
    const int d0 = blockIdx.x * 64;
    const int sbase = split * 256;

    float acc[4][4] = {};

    for (int s0 = sbase; s0 < sbase + 256; s0 += 32) {
#pragma unroll
        for (int l = 0; l < 8; l++) {
            int e = tid + l * 256;
            int sr = e >> 6, cc = e & 63;
            Ls[sr][cc] = L [(s0 + sr) * LSTRIDE + t0 + cc];
            Gs[sr][cc] = rL[(s0 + sr) * LSTRIDE + t0 + cc];
            Ts[sr][cc] = g_T[((b << 10) + s0 + sr) * DIM + d0 + cc];
            Rs[sr][cc] = g_R[((b << 10) + s0 + sr) * DIM + d0 + cc];
        }
        __syncthreads();
#pragma unroll
        for (int kk = 0; kk < 32; kk++) {
            float4 a  = *(const float4*)&Ls[kk][ty * 4];
            float4 ag = *(const float4*)&Gs[kk][ty * 4];
            float4 bt = *(const float4*)&Ts[kk][tx * 4];
            float4 br = *(const float4*)&Rs[kk][tx * 4];
            float av[4]  = {a.x, a.y, a.z, a.w};
            float agv[4] = {ag.x, ag.y, ag.z, ag.w};
            float bv[4]  = {bt.x, bt.y, bt.z, bt.w};
            float brv[4] = {br.x, br.y, br.z, br.w};
#pragma unroll
            for (int i = 0; i < 4; i++)
#pragma unroll
                for (int j = 0; j < 4; j++) {
                    acc[i][j] = fmaf(av[i],  bv[j],  acc[i][j]);
                    acc[i][j] = fmaf(agv[i], brv[j], acc[i][j]);
                }
        }
        __syncthreads();
    }

    float* dst = g_part[split];
#pragma unroll
    for (int i = 0; i < 4; i++) {
        float4 v = {acc[i][0], acc[i][1], acc[i][2], acc[i][3]};
        *(float4*)&dst[(b * TOUT + t0 + ty * 4 + i) * DIM + d0 + tx * 4] = v;
    }
}

// ---------------------------------------------------------------------------
// K5: deterministic split-K reduction
// ---------------------------------------------------------------------------
__global__ __launch_bounds__(256) void reduce_kernel(float* __restrict__ out)
{
    int idx = blockIdx.x * 256 + threadIdx.x;    // float4 index, 65536 total
    const float4* p0 = (const float4*)g_part[0];
    const float4* p1 = (const float4*)g_part[1];
    const float4* p2 = (const float4*)g_part[2];
    const float4* p3 = (const float4*)g_part[3];
    float4 a = p0[idx], b = p1[idx], c = p2[idx], d = p3[idx];
    float4 r;
    r.x = (a.x + b.x) + (c.x + d.x);
    r.y = (a.y + b.y) + (c.y + d.y);
    r.z = (a.z + b.z) + (c.z + d.z);
    r.w = (a.w + b.w) + (c.w + d.w);
    ((float4*)out)[idx] = r;
}

// ---------------------------------------------------------------------------
extern "C" void kernel_launch(void* const* d_in, const int* in_sizes, int n_in,
                              void* d_out, int out_size)
{
    const float* x       = (const float*)d_in[0];
    const float* Mw      = (const float*)d_in[1];
    const float* P       = (const float*)d_in[2];
    const float* Linker  = (const float*)d_in[3];
    const float* gamma   = (const float*)d_in[4];
    const float* beta    = (const float*)d_in[5];
    const float* resW    = (const float*)d_in[6];
    const float* rLinker = (const float*)d_in[7];
    float* out = (float*)d_out;

    param_kernel<<<DIM * DIM / 256, 256>>>(P);

    dim3 g1(DIM / 64, NROWS / 32);
    dual_gemm_kernel<<<g1, 128>>>(x, Mw, resW);

    ln_kernel<<<NROWS / 8, 256>>>(gamma, beta);

    dim3 g3(DIM / 16, NROWS / 64);
    tphi_kernel<<<g3, 128>>>();

    dim3 g4(DIM / 64, TOUT / 64, NBATCH * 4);
    linker_kernel<<<g4, 256>>>(Linker, rLinker);

    reduce_kernel<<<NBATCH * TOUT * DIM / 4 / 256, 256>>>(out);
}